// round 14
// baseline (speedup 1.0000x reference)
#include <cuda_runtime.h>
#include <cuda_fp16.h>
#include <math.h>

#define BATCH 8
#define SEQ   2048
#define DIM   1024
#define MSZ   (BATCH*SEQ)
typedef unsigned int u32;

#define NXD ((size_t)MSZ*DIM)
#define NPP ((size_t)BATCH*SEQ*SEQ)

// fp16 {hi,mid} planes, pre-scaled by OPSCALE (allocation-free rule)
__device__ __half g_qh[NXD], g_qm[NXD];
__device__ __half g_kh[NXD], g_km[NXD];
__device__ __half g_vth[NXD], g_vtm[NXD];   // v^T: [b][e][s]
__device__ __half g_ph[NPP], g_pm[NPP];

#define OPSCALE 64.0f
#define INVSC   (1.0f/4096.0f)

// ---------------- helpers ----------------
__device__ __forceinline__ u32 smem_u32(const void* p) {
    u32 a;
    asm("{ .reg .u64 t; cvta.to.shared.u64 t, %1; cvt.u32.u64 %0, t; }" : "=r"(a) : "l"(p));
    return a;
}
__device__ __forceinline__ void cp16(u32 s, const void* g) {
    asm volatile("cp.async.cg.shared.global [%0], [%1], 16;" :: "r"(s), "l"(g));
}
#define CP_COMMIT() asm volatile("cp.async.commit_group;" ::: "memory")
#define CP_WAIT0()  asm volatile("cp.async.wait_group 0;" ::: "memory")
#define CP_WAIT1()  asm volatile("cp.async.wait_group 1;" ::: "memory")

__device__ __forceinline__ void mma16(float* c, const u32* a, u32 b0, u32 b1) {
    asm volatile(
        "mma.sync.aligned.m16n8k16.row.col.f32.f16.f16.f32 "
        "{%0,%1,%2,%3}, {%4,%5,%6,%7}, {%8,%9}, {%0,%1,%2,%3};"
        : "+f"(c[0]), "+f"(c[1]), "+f"(c[2]), "+f"(c[3])
        : "r"(a[0]), "r"(a[1]), "r"(a[2]), "r"(a[3]), "r"(b0), "r"(b1));
}
__device__ __forceinline__ void split2(float x0, float x1, u32& hp, u32& mp) {
    __half2 h = __floats2half2_rn(x0, x1);
    float2 hf = __half22float2(h);
    __half2 m = __floats2half2_rn(x0 - hf.x, x1 - hf.y);
    hp = *(u32*)&h; mp = *(u32*)&m;
}

// ---------------------------------------------------------------------------
// gemm_proj (R13-proven): raw fp32 NT gemm -> fp16 {h,m} plane outputs.
// CTA 128x128, KC=32, 256 thr (8 warps 2m x 4n), warp 64x32.
// ---------------------------------------------------------------------------
#define LDH 20                          // proj plane row stride in u32
#define PLANE_U32 (128*LDH)             // 2560 u32
#define SMEM_PROJ (2*4*PLANE_U32*4)     // 81920 B

__global__ __launch_bounds__(256, 1) void gemm_proj(
    const float* __restrict__ A, const float* __restrict__ B,
    const float* __restrict__ bias, int biasRow,
    __half* __restrict__ Ch, __half* __restrict__ Cm, int K,
    size_t sA, size_t sB, size_t sC, int ldc)
{
    extern __shared__ u32 pl[];
    const int tid = threadIdx.x;
    const int wid = tid >> 5, lane = tid & 31;
    const int g = lane >> 2, tig = lane & 3;
    const int wm = (wid >> 2) * 64, wn = (wid & 3) * 32;
    const int z = blockIdx.z;

    const float* Ab = A + z * sA + (size_t)(blockIdx.y * 128) * K;
    const float* Bb = B + z * sB + (size_t)(blockIdx.x * 128) * K;

    const int lr  = tid >> 3;
    const int lc4 = (tid & 7) * 4;

    float acc[4][4][4];
#pragma unroll
    for (int mi = 0; mi < 4; mi++)
#pragma unroll
        for (int ni = 0; ni < 4; ni++)
#pragma unroll
            for (int r = 0; r < 4; r++) acc[mi][ni][r] = 0.0f;

    const int nch = K / 32;
    float4 ra[4], rb[4];

    auto load_regs = [&](int c) {
        const int k0 = c * 32;
#pragma unroll
        for (int i = 0; i < 4; i++) {
            const int row = lr + i * 32;
            ra[i] = *(const float4*)(Ab + (size_t)row * K + k0 + lc4);
            rb[i] = *(const float4*)(Bb + (size_t)row * K + k0 + lc4);
        }
    };
    auto convert_store = [&](int buf) {
        u32* Ah = pl + (buf * 4 + 0) * PLANE_U32;
        u32* Am = pl + (buf * 4 + 1) * PLANE_U32;
        u32* Bh = pl + (buf * 4 + 2) * PLANE_U32;
        u32* Bm = pl + (buf * 4 + 3) * PLANE_U32;
#pragma unroll
        for (int i = 0; i < 4; i++) {
            const int poff = (lr + i * 32) * LDH + (lc4 >> 1);
            u32 h0, m0, h1, m1;
            split2(ra[i].x * OPSCALE, ra[i].y * OPSCALE, h0, m0);
            split2(ra[i].z * OPSCALE, ra[i].w * OPSCALE, h1, m1);
            *(uint2*)(Ah + poff) = make_uint2(h0, h1);
            *(uint2*)(Am + poff) = make_uint2(m0, m1);
            split2(rb[i].x * OPSCALE, rb[i].y * OPSCALE, h0, m0);
            split2(rb[i].z * OPSCALE, rb[i].w * OPSCALE, h1, m1);
            *(uint2*)(Bh + poff) = make_uint2(h0, h1);
            *(uint2*)(Bm + poff) = make_uint2(m0, m1);
        }
    };

    load_regs(0);
    convert_store(0);
    __syncthreads();
    if (nch > 1) load_regs(1);

    for (int c = 0; c < nch; c++) {
        const int p = c & 1;
        if (c + 1 < nch) convert_store(p ^ 1);
        if (c + 2 < nch) load_regs(c + 2);

        const u32* Ah = pl + (p * 4 + 0) * PLANE_U32;
        const u32* Am = pl + (p * 4 + 1) * PLANE_U32;
        const u32* Bh = pl + (p * 4 + 2) * PLANE_U32;
        const u32* Bm = pl + (p * 4 + 3) * PLANE_U32;

#pragma unroll
        for (int ks = 0; ks < 2; ks++) {
            const int kc = ks * 8 + tig;
            u32 ah[4][4], am[4][4];
#pragma unroll
            for (int mi = 0; mi < 4; mi++) {
                const int r0 = (wm + mi * 16 + g) * LDH;
                const int r1 = r0 + 8 * LDH;
                ah[mi][0] = Ah[r0 + kc]; ah[mi][1] = Ah[r1 + kc];
                ah[mi][2] = Ah[r0 + kc + 4]; ah[mi][3] = Ah[r1 + kc + 4];
                am[mi][0] = Am[r0 + kc]; am[mi][1] = Am[r1 + kc];
                am[mi][2] = Am[r0 + kc + 4]; am[mi][3] = Am[r1 + kc + 4];
            }
#pragma unroll
            for (int ni = 0; ni < 4; ni++) {
                const int rn = (wn + ni * 8 + g) * LDH;
                const u32 bh0 = Bh[rn + kc], bh1 = Bh[rn + kc + 4];
                const u32 bm0 = Bm[rn + kc], bm1 = Bm[rn + kc + 4];
#pragma unroll
                for (int mi = 0; mi < 4; mi++) mma16(acc[mi][ni], ah[mi], bh0, bh1);
#pragma unroll
                for (int mi = 0; mi < 4; mi++) mma16(acc[mi][ni], am[mi], bh0, bh1);
#pragma unroll
                for (int mi = 0; mi < 4; mi++) mma16(acc[mi][ni], ah[mi], bm0, bm1);
            }
        }
        __syncthreads();
    }

    // epilogue: bias -> fp16 {h,m} planes (scaled by OPSCALE)
    __half* Chz = Ch + z * sC;
    __half* Cmz = Cm + z * sC;
#pragma unroll
    for (int mi = 0; mi < 4; mi++) {
        const int row0 = blockIdx.y * 128 + wm + mi * 16 + g;
        const float br0 = (bias && biasRow) ? bias[row0] : 0.0f;
        const float br1 = (bias && biasRow) ? bias[row0 + 8] : 0.0f;
#pragma unroll
        for (int ni = 0; ni < 4; ni++) {
            const int col0 = blockIdx.x * 128 + wn + ni * 8 + tig * 2;
            float v[4];
            v[0] = acc[mi][ni][0] * INVSC; v[1] = acc[mi][ni][1] * INVSC;
            v[2] = acc[mi][ni][2] * INVSC; v[3] = acc[mi][ni][3] * INVSC;
            if (bias) {
                if (biasRow) { v[0] += br0; v[1] += br0; v[2] += br1; v[3] += br1; }
                else {
                    const float b0 = bias[col0], b1 = bias[col0 + 1];
                    v[0] += b0; v[1] += b1; v[2] += b0; v[3] += b1;
                }
            }
            u32 h0, m0, h1, m1;
            split2(v[0] * OPSCALE, v[1] * OPSCALE, h0, m0);
            split2(v[2] * OPSCALE, v[3] * OPSCALE, h1, m1);
            const size_t o0 = (size_t)row0 * ldc + col0;
            const size_t o1 = (size_t)(row0 + 8) * ldc + col0;
            *(u32*)(Chz + o0) = h0; *(u32*)(Cmz + o0) = m0;
            *(u32*)(Chz + o1) = h1; *(u32*)(Cmz + o1) = m1;
        }
    }
}

// ---------------------------------------------------------------------------
// gemm_big v2: fp16 {h,m} plane operands, fp32 out.
// CTA 128x128, KC=64 (4 k16 steps), 256 thr (8 warps 2m x 4n), warp 64x32.
// 3-stage cp.async pipeline (wait_group 1, prefetch distance 2), 1 CTA/SM.
// Single-pass MMA (ah+am live). nprod: 3 = hh+mh+hm (QK), 2 = hh+mh (PV).
// ---------------------------------------------------------------------------
#define LDB 36                          // big plane row stride in u32 (64 fp16 + pad)
#define PLB (128*LDB)                   // 4608 u32 per plane (18432 B)
#define BIG_STAGE (4*PLB)               // u32 per stage
#define SMEM_BIG (3*BIG_STAGE*4)        // 221184 B

__global__ __launch_bounds__(256, 1) void gemm_big(
    const __half* __restrict__ Ahg, const __half* __restrict__ Amg,
    const __half* __restrict__ Bhg, const __half* __restrict__ Bmg,
    float* __restrict__ C, int K, float scale,
    size_t sA, size_t sB, size_t sC, int ldc, int nprod)
{
    extern __shared__ u32 pl[];
    const u32 sbase = smem_u32(pl);
    const int tid = threadIdx.x;
    const int wid = tid >> 5, lane = tid & 31;
    const int g = lane >> 2, tig = lane & 3;
    const int wm = (wid >> 2) * 64, wn = (wid & 3) * 32;
    const int z = blockIdx.z;

    const __half* gp[4] = { Ahg + z * sA + (size_t)(blockIdx.y * 128) * K,
                            Amg + z * sA + (size_t)(blockIdx.y * 128) * K,
                            Bhg + z * sB + (size_t)(blockIdx.x * 128) * K,
                            Bmg + z * sB + (size_t)(blockIdx.x * 128) * K };

    float acc[4][4][4];
#pragma unroll
    for (int mi = 0; mi < 4; mi++)
#pragma unroll
        for (int ni = 0; ni < 4; ni++)
#pragma unroll
            for (int r = 0; r < 4; r++) acc[mi][ni][r] = 0.0f;

    const int nch = K / 64;
    const int npl = (nprod == 3) ? 4 : 3;

    // fill stage `buf` with chunk c: per plane 1024 cp16 slots (128 rows x 8)
    auto issue = [&](int c, int buf) {
        const int k0 = c * 64;                       // halves
        const u32 s0 = sbase + (u32)(buf * BIG_STAGE) * 4;
        const int row = tid >> 3;                    // slot mapping: 4 slots/thread/plane
        const int c16 = (tid & 7) * 16;              // byte col within 128B row
        for (int p = 0; p < npl; p++) {
            const __half* gb = gp[p];
            const u32 sp = s0 + (u32)(p * PLB) * 4;
#pragma unroll
            for (int i = 0; i < 4; i++) {
                const int r = row + i * 32;
                cp16(sp + (u32)(r * LDB) * 4 + c16,
                     gb + (size_t)r * K + k0 + (c16 >> 1));
            }
        }
        CP_COMMIT();
    };

    issue(0, 0);
    if (nch > 1) issue(1, 1);

    for (int c = 0; c < nch; c++) {
        CP_WAIT1();
        __syncthreads();                 // stage c%3 data visible to all
        if (c + 2 < nch) issue(c + 2, (c + 2) % 3);

        const u32* Ah = pl + (c % 3) * BIG_STAGE + 0 * PLB;
        const u32* Am = pl + (c % 3) * BIG_STAGE + 1 * PLB;
        const u32* Bh = pl + (c % 3) * BIG_STAGE + 2 * PLB;
        const u32* Bm = pl + (c % 3) * BIG_STAGE + 3 * PLB;

#pragma unroll
        for (int ks = 0; ks < 4; ks++) {
            const int kc = ks * 8 + tig;
            u32 ah[4][4], am[4][4];
#pragma unroll
            for (int mi = 0; mi < 4; mi++) {
                const int r0 = (wm + mi * 16 + g) * LDB;
                const int r1 = r0 + 8 * LDB;
                ah[mi][0] = Ah[r0 + kc]; ah[mi][1] = Ah[r1 + kc];
                ah[mi][2] = Ah[r0 + kc + 4]; ah[mi][3] = Ah[r1 + kc + 4];
                am[mi][0] = Am[r0 + kc]; am[mi][1] = Am[r1 + kc];
                am[mi][2] = Am[r0 + kc + 4]; am[mi][3] = Am[r1 + kc + 4];
            }
#pragma unroll
            for (int ni = 0; ni < 4; ni++) {
                const int rn = (wn + ni * 8 + g) * LDB;
                const u32 bh0 = Bh[rn + kc], bh1 = Bh[rn + kc + 4];
#pragma unroll
                for (int mi = 0; mi < 4; mi++) mma16(acc[mi][ni], ah[mi], bh0, bh1);
#pragma unroll
                for (int mi = 0; mi < 4; mi++) mma16(acc[mi][ni], am[mi], bh0, bh1);
                if (nprod == 3) {
                    const u32 bm0 = Bm[rn + kc], bm1 = Bm[rn + kc + 4];
#pragma unroll
                    for (int mi = 0; mi < 4; mi++) mma16(acc[mi][ni], ah[mi], bm0, bm1);
                }
            }
        }
        __syncthreads();                 // reads done before stage reuse
    }

    // epilogue
    float* Cz = C + z * sC;
#pragma unroll
    for (int mi = 0; mi < 4; mi++) {
        const int row0 = blockIdx.y * 128 + wm + mi * 16 + g;
#pragma unroll
        for (int ni = 0; ni < 4; ni++) {
            const int col0 = blockIdx.x * 128 + wn + ni * 8 + tig * 2;
            float2 v0, v1;
            v0.x = acc[mi][ni][0] * scale; v0.y = acc[mi][ni][1] * scale;
            v1.x = acc[mi][ni][2] * scale; v1.y = acc[mi][ni][3] * scale;
            *(float2*)(Cz + (size_t)row0 * ldc + col0) = v0;
            *(float2*)(Cz + (size_t)(row0 + 8) * ldc + col0) = v1;
        }
    }
}

// ---------------------------------------------------------------------------
// In-place row softmax + fp16 {h,m} plane output (scaled by OPSCALE).
// ---------------------------------------------------------------------------
__global__ __launch_bounds__(256) void softmax_k(float* __restrict__ P,
    __half* __restrict__ ph, __half* __restrict__ pm)
{
    const size_t base = (size_t)blockIdx.x * SEQ;
    float* p = P + base;
    const int tid = threadIdx.x, lane = tid & 31, wid = tid >> 5;
    float4 a = ((const float4*)p)[tid * 2 + 0];
    float4 b = ((const float4*)p)[tid * 2 + 1];
    float x[8] = {a.x, a.y, a.z, a.w, b.x, b.y, b.z, b.w};
    __shared__ float red[8];

    float m = -INFINITY;
#pragma unroll
    for (int i = 0; i < 8; i++) m = fmaxf(m, x[i]);
#pragma unroll
    for (int o = 16; o > 0; o >>= 1) m = fmaxf(m, __shfl_xor_sync(0xffffffffu, m, o));
    if (lane == 0) red[wid] = m;
    __syncthreads();
    float mr = -INFINITY;
#pragma unroll
    for (int i = 0; i < 8; i++) mr = fmaxf(mr, red[i]);
    __syncthreads();

    float s = 0.0f;
#pragma unroll
    for (int i = 0; i < 8; i++) { x[i] = expf(x[i] - mr); s += x[i]; }
#pragma unroll
    for (int o = 16; o > 0; o >>= 1) s += __shfl_xor_sync(0xffffffffu, s, o);
    if (lane == 0) red[wid] = s;
    __syncthreads();
    float tot = 0.0f;
#pragma unroll
    for (int i = 0; i < 8; i++) tot += red[i];
    const float inv = 1.0f / tot;

    float4 o0, o1;
    o0.x = x[0] * inv; o0.y = x[1] * inv; o0.z = x[2] * inv; o0.w = x[3] * inv;
    o1.x = x[4] * inv; o1.y = x[5] * inv; o1.z = x[6] * inv; o1.w = x[7] * inv;
    ((float4*)p)[tid * 2 + 0] = o0;
    ((float4*)p)[tid * 2 + 1] = o1;

    float y[8] = {o0.x, o0.y, o0.z, o0.w, o1.x, o1.y, o1.z, o1.w};
#pragma unroll
    for (int i = 0; i < 8; i += 2) {
        u32 hp, mp;
        split2(y[i] * OPSCALE, y[i + 1] * OPSCALE, hp, mp);
        const size_t off = base + tid * 8 + i;
        *(u32*)(ph + off) = hp;
        *(u32*)(pm + off) = mp;
    }
}

// ---------------------------------------------------------------------------
extern "C" void kernel_launch(void* const* d_in, const int* in_sizes, int n_in,
                              void* d_out, int out_size)
{
    const float* query = (const float*)d_in[0];
    const float* key   = (const float*)d_in[1];
    const float* value = (const float*)d_in[2];
    const float* Wq = (const float*)d_in[3]; const float* bq = (const float*)d_in[4];
    const float* Wk = (const float*)d_in[5]; const float* bk = (const float*)d_in[6];
    const float* Wv = (const float*)d_in[7]; const float* bv = (const float*)d_in[8];

    float* out_attn = (float*)d_out;
    float* out_smax = (float*)d_out + (size_t)MSZ * DIM;

    __half *qh, *qm, *kh, *km, *vth, *vtm, *ph, *pm;
    cudaGetSymbolAddress((void**)&qh,  g_qh);  cudaGetSymbolAddress((void**)&qm,  g_qm);
    cudaGetSymbolAddress((void**)&kh,  g_kh);  cudaGetSymbolAddress((void**)&km,  g_km);
    cudaGetSymbolAddress((void**)&vth, g_vth); cudaGetSymbolAddress((void**)&vtm, g_vtm);
    cudaGetSymbolAddress((void**)&ph,  g_ph);  cudaGetSymbolAddress((void**)&pm,  g_pm);

    cudaFuncSetAttribute(gemm_proj, cudaFuncAttributeMaxDynamicSharedMemorySize, SMEM_PROJ);
    cudaFuncSetAttribute(gemm_big,  cudaFuncAttributeMaxDynamicSharedMemorySize, SMEM_BIG);

    // 1) q/k projections -> fp16 planes
    {
        dim3 grid(DIM / 128, MSZ / 128, 1);
        gemm_proj<<<grid, 256, SMEM_PROJ>>>(query, Wq, bq, 0, qh, qm, DIM, 0, 0, 0, DIM);
        gemm_proj<<<grid, 256, SMEM_PROJ>>>(key,   Wk, bk, 0, kh, km, DIM, 0, 0, 0, DIM);
    }
    // 2) vT[b,e,s] = Wv[e,:] . value[b,s,:] + bv[e] -> planes
    {
        dim3 grid(SEQ / 128, DIM / 128, BATCH);
        gemm_proj<<<grid, 256, SMEM_PROJ>>>(Wv, value, bv, 1, vth, vtm, DIM,
                                            0, (size_t)SEQ * DIM, (size_t)DIM * SEQ, SEQ);
    }
    // 3) scores = 10 * q @ k^T   (3 products)
    {
        dim3 grid(SEQ / 128, SEQ / 128, BATCH);
        gemm_big<<<grid, 256, SMEM_BIG>>>(qh, qm, kh, km, out_smax, DIM, 10.0f * INVSC,
                                          (size_t)SEQ * DIM, (size_t)SEQ * DIM,
                                          (size_t)SEQ * SEQ, SEQ, 3);
    }
    // 4) softmax in place + P planes
    softmax_k<<<MSZ, 256>>>(out_smax, ph, pm);
    // 5) out = P @ vT^T   (2 products: hh + mh; v-mid plane never loaded)
    {
        dim3 grid(DIM / 128, SEQ / 128, BATCH);
        gemm_big<<<grid, 256, SMEM_BIG>>>(ph, pm, vth, vtm, out_attn, SEQ, INVSC,
                                          (size_t)SEQ * SEQ, (size_t)DIM * SEQ,
                                          (size_t)SEQ * DIM, DIM, 2);
    }
}

// round 16
// speedup vs baseline: 1.0221x; 1.0221x over previous
#include <cuda_runtime.h>
#include <cuda_fp16.h>
#include <math.h>

#define BATCH 8
#define SEQ   2048
#define DIM   1024
#define MSZ   (BATCH*SEQ)
typedef unsigned int u32;

#define NXD ((size_t)MSZ*DIM)
#define NPP ((size_t)BATCH*SEQ*SEQ)

// fp16 {hi,mid} planes, pre-scaled by OPSCALE (allocation-free rule)
__device__ __half g_qh[NXD], g_qm[NXD];
__device__ __half g_kh[NXD], g_km[NXD];
__device__ __half g_vth[NXD], g_vtm[NXD];   // v^T: [b][e][s]
__device__ __half g_ph[NPP], g_pm[NPP];

#define OPSCALE 64.0f
#define INVSC   (1.0f/4096.0f)

// ---------------- helpers ----------------
__device__ __forceinline__ u32 smem_u32(const void* p) {
    u32 a;
    asm("{ .reg .u64 t; cvta.to.shared.u64 t, %1; cvt.u32.u64 %0, t; }" : "=r"(a) : "l"(p));
    return a;
}
__device__ __forceinline__ void cp16(u32 s, const void* g) {
    asm volatile("cp.async.cg.shared.global [%0], [%1], 16;" :: "r"(s), "l"(g));
}
#define CP_COMMIT() asm volatile("cp.async.commit_group;" ::: "memory")
#define CP_WAIT0()  asm volatile("cp.async.wait_group 0;" ::: "memory")

__device__ __forceinline__ void mma16(float* c, const u32* a, u32 b0, u32 b1) {
    asm volatile(
        "mma.sync.aligned.m16n8k16.row.col.f32.f16.f16.f32 "
        "{%0,%1,%2,%3}, {%4,%5,%6,%7}, {%8,%9}, {%0,%1,%2,%3};"
        : "+f"(c[0]), "+f"(c[1]), "+f"(c[2]), "+f"(c[3])
        : "r"(a[0]), "r"(a[1]), "r"(a[2]), "r"(a[3]), "r"(b0), "r"(b1));
}
#define LDSM4(r, addr) \
    asm volatile("ldmatrix.sync.aligned.m8n8.x4.shared.b16 {%0,%1,%2,%3}, [%4];" \
        : "=r"((r)[0]), "=r"((r)[1]), "=r"((r)[2]), "=r"((r)[3]) : "r"(addr))

__device__ __forceinline__ void split2(float x0, float x1, u32& hp, u32& mp) {
    __half2 h = __floats2half2_rn(x0, x1);
    float2 hf = __half22float2(h);
    __half2 m = __floats2half2_rn(x0 - hf.x, x1 - hf.y);
    hp = *(u32*)&h; mp = *(u32*)&m;
}

// plane geometry (shared by both gemms): k-contiguous fp16 rows,
// row stride LDH=20 u32 = 80 B (64 B data for KC=32 + 16 B pad)
#define LDH 20
#define LDH_B 80
#define PLANE_U32 (128*LDH)             // 2560 u32 (10240 B)
#define SMEM_BYTES (2*4*PLANE_U32*4)    // 2 bufs x {Ah,Am,Bh,Bm} = 81920 B

// ---------------------------------------------------------------------------
// gemm_proj: raw fp32 NT gemm -> fp16 {h,m} plane outputs (scaled).
// CTA 128x128, KC=32, 256 thr (8 warps 2m x 4n), warp 64x32. ldmatrix frags.
// ---------------------------------------------------------------------------
__global__ __launch_bounds__(256, 1) void gemm_proj(
    const float* __restrict__ A, const float* __restrict__ B,
    const float* __restrict__ bias, int biasRow,
    __half* __restrict__ Ch, __half* __restrict__ Cm, int K,
    size_t sA, size_t sB, size_t sC, int ldc)
{
    extern __shared__ u32 pl[];
    const u32 sbase = smem_u32(pl);
    const int tid = threadIdx.x;
    const int wid = tid >> 5, lane = tid & 31;
    const int g = lane >> 2, tig = lane & 3;
    const int wm = (wid >> 2) * 64, wn = (wid & 3) * 32;
    const int z = blockIdx.z;

    const float* Ab = A + z * sA + (size_t)(blockIdx.y * 128) * K;
    const float* Bb = B + z * sB + (size_t)(blockIdx.x * 128) * K;

    const int lr  = tid >> 3;
    const int lc4 = (tid & 7) * 4;

    // ldmatrix lane offsets (bytes within a plane)
    const u32 aoff = (u32)((wm + (lane & 15)) * LDH_B + (lane >> 4) * 16);
    const u32 boff = (u32)((wn + ((lane >> 4) << 3) + (lane & 7)) * LDH_B
                           + ((lane >> 3) & 1) * 16);

    float acc[4][4][4];
#pragma unroll
    for (int mi = 0; mi < 4; mi++)
#pragma unroll
        for (int ni = 0; ni < 4; ni++)
#pragma unroll
            for (int r = 0; r < 4; r++) acc[mi][ni][r] = 0.0f;

    const int nch = K / 32;
    float4 ra[4], rb[4];

    auto load_regs = [&](int c) {
        const int k0 = c * 32;
#pragma unroll
        for (int i = 0; i < 4; i++) {
            const int row = lr + i * 32;
            ra[i] = *(const float4*)(Ab + (size_t)row * K + k0 + lc4);
            rb[i] = *(const float4*)(Bb + (size_t)row * K + k0 + lc4);
        }
    };
    auto convert_store = [&](int buf) {
        u32* Ah = pl + (buf * 4 + 0) * PLANE_U32;
        u32* Am = pl + (buf * 4 + 1) * PLANE_U32;
        u32* Bh = pl + (buf * 4 + 2) * PLANE_U32;
        u32* Bm = pl + (buf * 4 + 3) * PLANE_U32;
#pragma unroll
        for (int i = 0; i < 4; i++) {
            const int poff = (lr + i * 32) * LDH + (lc4 >> 1);
            u32 h0, m0, h1, m1;
            split2(ra[i].x * OPSCALE, ra[i].y * OPSCALE, h0, m0);
            split2(ra[i].z * OPSCALE, ra[i].w * OPSCALE, h1, m1);
            *(uint2*)(Ah + poff) = make_uint2(h0, h1);
            *(uint2*)(Am + poff) = make_uint2(m0, m1);
            split2(rb[i].x * OPSCALE, rb[i].y * OPSCALE, h0, m0);
            split2(rb[i].z * OPSCALE, rb[i].w * OPSCALE, h1, m1);
            *(uint2*)(Bh + poff) = make_uint2(h0, h1);
            *(uint2*)(Bm + poff) = make_uint2(m0, m1);
        }
    };

    load_regs(0);
    convert_store(0);
    __syncthreads();
    if (nch > 1) load_regs(1);

    for (int c = 0; c < nch; c++) {
        const int p = c & 1;
        if (c + 1 < nch) convert_store(p ^ 1);
        if (c + 2 < nch) load_regs(c + 2);

        const u32 Ahb = sbase + (u32)((p * 4 + 0) * PLANE_U32) * 4 + aoff;
        const u32 Amb = sbase + (u32)((p * 4 + 1) * PLANE_U32) * 4 + aoff;
        const u32 Bhb = sbase + (u32)((p * 4 + 2) * PLANE_U32) * 4 + boff;
        const u32 Bmb = sbase + (u32)((p * 4 + 3) * PLANE_U32) * 4 + boff;

#pragma unroll
        for (int ks = 0; ks < 2; ks++) {
            const u32 kb = (u32)(ks * 32);
            u32 ah[4][4], am[4][4], bh[4][2], bm[4][2];
#pragma unroll
            for (int mi = 0; mi < 4; mi++) {
                LDSM4(ah[mi], Ahb + (u32)(mi * 16 * LDH_B) + kb);
                LDSM4(am[mi], Amb + (u32)(mi * 16 * LDH_B) + kb);
            }
#pragma unroll
            for (int pr = 0; pr < 2; pr++) {
                u32 t[4];
                LDSM4(t, Bhb + (u32)(pr * 16 * LDH_B) + kb);
                bh[pr*2][0] = t[0]; bh[pr*2][1] = t[1];
                bh[pr*2+1][0] = t[2]; bh[pr*2+1][1] = t[3];
                LDSM4(t, Bmb + (u32)(pr * 16 * LDH_B) + kb);
                bm[pr*2][0] = t[0]; bm[pr*2][1] = t[1];
                bm[pr*2+1][0] = t[2]; bm[pr*2+1][1] = t[3];
            }
#pragma unroll
            for (int ni = 0; ni < 4; ni++)
#pragma unroll
                for (int mi = 0; mi < 4; mi++) mma16(acc[mi][ni], ah[mi], bh[ni][0], bh[ni][1]);
#pragma unroll
            for (int ni = 0; ni < 4; ni++)
#pragma unroll
                for (int mi = 0; mi < 4; mi++) mma16(acc[mi][ni], am[mi], bh[ni][0], bh[ni][1]);
#pragma unroll
            for (int ni = 0; ni < 4; ni++)
#pragma unroll
                for (int mi = 0; mi < 4; mi++) mma16(acc[mi][ni], ah[mi], bm[ni][0], bm[ni][1]);
        }
        __syncthreads();
    }

    // epilogue: bias -> fp16 {h,m} planes (scaled by OPSCALE)
    __half* Chz = Ch + z * sC;
    __half* Cmz = Cm + z * sC;
#pragma unroll
    for (int mi = 0; mi < 4; mi++) {
        const int row0 = blockIdx.y * 128 + wm + mi * 16 + g;
        const float br0 = (bias && biasRow) ? bias[row0] : 0.0f;
        const float br1 = (bias && biasRow) ? bias[row0 + 8] : 0.0f;
#pragma unroll
        for (int ni = 0; ni < 4; ni++) {
            const int col0 = blockIdx.x * 128 + wn + ni * 8 + tig * 2;
            float v[4];
            v[0] = acc[mi][ni][0] * INVSC; v[1] = acc[mi][ni][1] * INVSC;
            v[2] = acc[mi][ni][2] * INVSC; v[3] = acc[mi][ni][3] * INVSC;
            if (bias) {
                if (biasRow) { v[0] += br0; v[1] += br0; v[2] += br1; v[3] += br1; }
                else {
                    const float b0 = bias[col0], b1 = bias[col0 + 1];
                    v[0] += b0; v[1] += b1; v[2] += b0; v[3] += b1;
                }
            }
            u32 h0, m0, h1, m1;
            split2(v[0] * OPSCALE, v[1] * OPSCALE, h0, m0);
            split2(v[2] * OPSCALE, v[3] * OPSCALE, h1, m1);
            const size_t o0 = (size_t)row0 * ldc + col0;
            const size_t o1 = (size_t)(row0 + 8) * ldc + col0;
            *(u32*)(Chz + o0) = h0; *(u32*)(Cmz + o0) = m0;
            *(u32*)(Chz + o1) = h1; *(u32*)(Cmz + o1) = m1;
        }
    }
}

// ---------------------------------------------------------------------------
// gemm_big: fp16 {h,m} plane operands (pre-scaled), fp32 out.
// CTA 128x128, KC=32, 256 thr, warp 64x32. cp.async plane fill, double
// buffered; ldmatrix fragment loads; single-pass MMA. 1 CTA/SM.
// nprod: 3 = hh+mh+hm (QK), 2 = hh+mh (PV: Bm never loaded).
// ---------------------------------------------------------------------------
__global__ __launch_bounds__(256, 1) void gemm_big(
    const __half* __restrict__ Ahg, const __half* __restrict__ Amg,
    const __half* __restrict__ Bhg, const __half* __restrict__ Bmg,
    float* __restrict__ C, int K, float scale,
    size_t sA, size_t sB, size_t sC, int ldc, int nprod)
{
    extern __shared__ u32 pl[];
    const u32 sbase = smem_u32(pl);
    const int tid = threadIdx.x;
    const int wid = tid >> 5, lane = tid & 31;
    const int g = lane >> 2, tig = lane & 3;
    const int wm = (wid >> 2) * 64, wn = (wid & 3) * 32;
    const int z = blockIdx.z;

    const __half* Ab[2] = { Ahg + z * sA + (size_t)(blockIdx.y * 128) * K,
                            Amg + z * sA + (size_t)(blockIdx.y * 128) * K };
    const __half* Bb[2] = { Bhg + z * sB + (size_t)(blockIdx.x * 128) * K,
                            Bmg + z * sB + (size_t)(blockIdx.x * 128) * K };

    const u32 aoff = (u32)((wm + (lane & 15)) * LDH_B + (lane >> 4) * 16);
    const u32 boff = (u32)((wn + ((lane >> 4) << 3) + (lane & 7)) * LDH_B
                           + ((lane >> 3) & 1) * 16);

    float acc[4][4][4];
#pragma unroll
    for (int mi = 0; mi < 4; mi++)
#pragma unroll
        for (int ni = 0; ni < 4; ni++)
#pragma unroll
            for (int r = 0; r < 4; r++) acc[mi][ni][r] = 0.0f;

    const int nch = K / 32;
    const int nbp = (nprod == 3) ? 2 : 1;

    auto issue = [&](int c, int buf) {
        const int k0 = c * 32;
        const u32 s0 = sbase + (u32)(buf * 4 * PLANE_U32) * 4;
#pragma unroll
        for (int i = 0; i < 2; i++) {
            const int slot = tid + i * 256;          // 0..511
            const int row = slot >> 2;               // 0..127
            const int c4 = (slot & 3) * 4;           // u32 col
            const u32 soff = (u32)(row * LDH + c4) * 4;
            const size_t goff = (size_t)row * K + k0 + c4 * 2;
            cp16(s0 + 0 * PLANE_U32 * 4 + soff, Ab[0] + goff);
            cp16(s0 + 1 * PLANE_U32 * 4 + soff, Ab[1] + goff);
            cp16(s0 + 2 * PLANE_U32 * 4 + soff, Bb[0] + goff);
            if (nbp == 2) cp16(s0 + 3 * PLANE_U32 * 4 + soff, Bb[1] + goff);
        }
        CP_COMMIT();
    };

    issue(0, 0);

    for (int c = 0; c < nch; c++) {
        const int p = c & 1;
        CP_WAIT0();
        __syncthreads();
        if (c + 1 < nch) issue(c + 1, p ^ 1);

        const u32 Ahb = sbase + (u32)((p * 4 + 0) * PLANE_U32) * 4 + aoff;
        const u32 Amb = sbase + (u32)((p * 4 + 1) * PLANE_U32) * 4 + aoff;
        const u32 Bhb = sbase + (u32)((p * 4 + 2) * PLANE_U32) * 4 + boff;
        const u32 Bmb = sbase + (u32)((p * 4 + 3) * PLANE_U32) * 4 + boff;

#pragma unroll
        for (int ks = 0; ks < 2; ks++) {
            const u32 kb = (u32)(ks * 32);
            u32 ah[4][4], am[4][4], bh[4][2], bm[4][2];
#pragma unroll
            for (int mi = 0; mi < 4; mi++) {
                LDSM4(ah[mi], Ahb + (u32)(mi * 16 * LDH_B) + kb);
                LDSM4(am[mi], Amb + (u32)(mi * 16 * LDH_B) + kb);
            }
#pragma unroll
            for (int pr = 0; pr < 2; pr++) {
                u32 t[4];
                LDSM4(t, Bhb + (u32)(pr * 16 * LDH_B) + kb);
                bh[pr*2][0] = t[0]; bh[pr*2][1] = t[1];
                bh[pr*2+1][0] = t[2]; bh[pr*2+1][1] = t[3];
                if (nprod == 3) {
                    LDSM4(t, Bmb + (u32)(pr * 16 * LDH_B) + kb);
                    bm[pr*2][0] = t[0]; bm[pr*2][1] = t[1];
                    bm[pr*2+1][0] = t[2]; bm[pr*2+1][1] = t[3];
                }
            }
#pragma unroll
            for (int ni = 0; ni < 4; ni++)
#pragma unroll
                for (int mi = 0; mi < 4; mi++) mma16(acc[mi][ni], ah[mi], bh[ni][0], bh[ni][1]);
#pragma unroll
            for (int ni = 0; ni < 4; ni++)
#pragma unroll
                for (int mi = 0; mi < 4; mi++) mma16(acc[mi][ni], am[mi], bh[ni][0], bh[ni][1]);
            if (nprod == 3) {
#pragma unroll
                for (int ni = 0; ni < 4; ni++)
#pragma unroll
                    for (int mi = 0; mi < 4; mi++) mma16(acc[mi][ni], ah[mi], bm[ni][0], bm[ni][1]);
            }
        }
        __syncthreads();
    }

    // epilogue
    float* Cz = C + z * sC;
#pragma unroll
    for (int mi = 0; mi < 4; mi++) {
        const int row0 = blockIdx.y * 128 + wm + mi * 16 + g;
#pragma unroll
        for (int ni = 0; ni < 4; ni++) {
            const int col0 = blockIdx.x * 128 + wn + ni * 8 + tig * 2;
            float2 v0, v1;
            v0.x = acc[mi][ni][0] * scale; v0.y = acc[mi][ni][1] * scale;
            v1.x = acc[mi][ni][2] * scale; v1.y = acc[mi][ni][3] * scale;
            *(float2*)(Cz + (size_t)row0 * ldc + col0) = v0;
            *(float2*)(Cz + (size_t)(row0 + 8) * ldc + col0) = v1;
        }
    }
}

// ---------------------------------------------------------------------------
// In-place row softmax + fp16 {h,m} plane output (scaled by OPSCALE).
// ---------------------------------------------------------------------------
__global__ __launch_bounds__(256) void softmax_k(float* __restrict__ P,
    __half* __restrict__ ph, __half* __restrict__ pm)
{
    const size_t base = (size_t)blockIdx.x * SEQ;
    float* p = P + base;
    const int tid = threadIdx.x, lane = tid & 31, wid = tid >> 5;
    float4 a = ((const float4*)p)[tid * 2 + 0];
    float4 b = ((const float4*)p)[tid * 2 + 1];
    float x[8] = {a.x, a.y, a.z, a.w, b.x, b.y, b.z, b.w};
    __shared__ float red[8];

    float m = -INFINITY;
#pragma unroll
    for (int i = 0; i < 8; i++) m = fmaxf(m, x[i]);
#pragma unroll
    for (int o = 16; o > 0; o >>= 1) m = fmaxf(m, __shfl_xor_sync(0xffffffffu, m, o));
    if (lane == 0) red[wid] = m;
    __syncthreads();
    float mr = -INFINITY;
#pragma unroll
    for (int i = 0; i < 8; i++) mr = fmaxf(mr, red[i]);
    __syncthreads();

    float s = 0.0f;
#pragma unroll
    for (int i = 0; i < 8; i++) { x[i] = expf(x[i] - mr); s += x[i]; }
#pragma unroll
    for (int o = 16; o > 0; o >>= 1) s += __shfl_xor_sync(0xffffffffu, s, o);
    if (lane == 0) red[wid] = s;
    __syncthreads();
    float tot = 0.0f;
#pragma unroll
    for (int i = 0; i < 8; i++) tot += red[i];
    const float inv = 1.0f / tot;

    float4 o0, o1;
    o0.x = x[0] * inv; o0.y = x[1] * inv; o0.z = x[2] * inv; o0.w = x[3] * inv;
    o1.x = x[4] * inv; o1.y = x[5] * inv; o1.z = x[6] * inv; o1.w = x[7] * inv;
    ((float4*)p)[tid * 2 + 0] = o0;
    ((float4*)p)[tid * 2 + 1] = o1;

    float y[8] = {o0.x, o0.y, o0.z, o0.w, o1.x, o1.y, o1.z, o1.w};
#pragma unroll
    for (int i = 0; i < 8; i += 2) {
        u32 hp, mp;
        split2(y[i] * OPSCALE, y[i + 1] * OPSCALE, hp, mp);
        const size_t off = base + tid * 8 + i;
        *(u32*)(ph + off) = hp;
        *(u32*)(pm + off) = mp;
    }
}

// ---------------------------------------------------------------------------
extern "C" void kernel_launch(void* const* d_in, const int* in_sizes, int n_in,
                              void* d_out, int out_size)
{
    const float* query = (const float*)d_in[0];
    const float* key   = (const float*)d_in[1];
    const float* value = (const float*)d_in[2];
    const float* Wq = (const float*)d_in[3]; const float* bq = (const float*)d_in[4];
    const float* Wk = (const float*)d_in[5]; const float* bk = (const float*)d_in[6];
    const float* Wv = (const float*)d_in[7]; const float* bv = (const float*)d_in[8];

    float* out_attn = (float*)d_out;
    float* out_smax = (float*)d_out + (size_t)MSZ * DIM;

    __half *qh, *qm, *kh, *km, *vth, *vtm, *ph, *pm;
    cudaGetSymbolAddress((void**)&qh,  g_qh);  cudaGetSymbolAddress((void**)&qm,  g_qm);
    cudaGetSymbolAddress((void**)&kh,  g_kh);  cudaGetSymbolAddress((void**)&km,  g_km);
    cudaGetSymbolAddress((void**)&vth, g_vth); cudaGetSymbolAddress((void**)&vtm, g_vtm);
    cudaGetSymbolAddress((void**)&ph,  g_ph);  cudaGetSymbolAddress((void**)&pm,  g_pm);

    cudaFuncSetAttribute(gemm_proj, cudaFuncAttributeMaxDynamicSharedMemorySize, SMEM_BYTES);
    cudaFuncSetAttribute(gemm_big,  cudaFuncAttributeMaxDynamicSharedMemorySize, SMEM_BYTES);

    // 1) q/k projections -> fp16 planes
    {
        dim3 grid(DIM / 128, MSZ / 128, 1);
        gemm_proj<<<grid, 256, SMEM_BYTES>>>(query, Wq, bq, 0, qh, qm, DIM, 0, 0, 0, DIM);
        gemm_proj<<<grid, 256, SMEM_BYTES>>>(key,   Wk, bk, 0, kh, km, DIM, 0, 0, 0, DIM);
    }
    // 2) vT[b,e,s] = Wv[e,:] . value[b,s,:] + bv[e] -> planes
    {
        dim3 grid(SEQ / 128, DIM / 128, BATCH);
        gemm_proj<<<grid, 256, SMEM_BYTES>>>(Wv, value, bv, 1, vth, vtm, DIM,
                                             0, (size_t)SEQ * DIM, (size_t)DIM * SEQ, SEQ);
    }
    // 3) scores = 10 * q @ k^T   (3 products)
    {
        dim3 grid(SEQ / 128, SEQ / 128, BATCH);
        gemm_big<<<grid, 256, SMEM_BYTES>>>(qh, qm, kh, km, out_smax, DIM, 10.0f * INVSC,
                                            (size_t)SEQ * DIM, (size_t)SEQ * DIM,
                                            (size_t)SEQ * SEQ, SEQ, 3);
    }
    // 4) softmax in place + P planes
    softmax_k<<<MSZ, 256>>>(out_smax, ph, pm);
    // 5) out = P @ vT^T   (2 products: hh + mh; v-mid plane never loaded)
    {
        dim3 grid(DIM / 128, SEQ / 128, BATCH);
        gemm_big<<<grid, 256, SMEM_BYTES>>>(ph, pm, vth, vtm, out_attn, SEQ, INVSC,
                                            (size_t)SEQ * SEQ, (size_t)DIM * SEQ,
                                            (size_t)SEQ * DIM, DIM, 2);
    }
}